// round 7
// baseline (speedup 1.0000x reference)
#include <cuda_runtime.h>
#include <cuda_bf16.h>
#include <math.h>

#define NN 50000
#define EE 1600000
#define D  128       // H*C
#define CH 32
#define NH 4
#define SCAN_BLOCKS 196        // ceil(NN/256)
#define HIST_BLOCKS 6250       // ceil(EE/256)
#define GEMM_BLOCKS 391        // ceil(NN/128)

// ---------------- scratch (device globals; no allocation allowed) ----------------
__device__ float g_xl[NN * D];
__device__ float g_xr[NN * D];
__device__ float g_h [NN * D];
__device__ int   g_rowptr[NN + 1];
__device__ int   g_cur[NN];          // counts, then scatter cursors
__device__ int2  g_edge[EE];         // (src, bitcast(ew)) sorted by dst
__device__ int   g_blocksums[256];
__device__ float g_partials[HIST_BLOCKS];
__device__ float g_mean;

// ---------------- shared GEMM body ----------------
// C[nrows x 128] = A[nrows x 128] * B[128 x 128], 256 threads, packed f32x2 FFMA
__device__ __forceinline__ void gemm_body(const float* __restrict__ A,
                                          const float* __restrict__ B,
                                          float* __restrict__ C,
                                          int nrows, int bid) {
    const int BM = 128, BK = 16;
    __shared__ float As[BK][BM];
    __shared__ float Bs[BK][128];
    int tid = threadIdx.x;                 // 256
    int block_row = bid * BM;
    int tcol = tid & 15;                   // 16 col groups
    int trow = tid >> 4;                   // 16 row groups x 8
    unsigned long long acc2[8][4];
    #pragma unroll
    for (int i = 0; i < 8; i++)
        #pragma unroll
        for (int j = 0; j < 4; j++) acc2[i][j] = 0ULL;

    for (int k0 = 0; k0 < 128; k0 += BK) {
        #pragma unroll
        for (int l = 0; l < 2; l++) {
            int idx = tid + l * 256;        // 0..511 float4s
            int ar  = idx >> 2;
            int ac4 = idx & 3;
            int grow = block_row + ar;
            float4 v = make_float4(0.f, 0.f, 0.f, 0.f);
            if (grow < nrows) v = *(const float4*)&A[grow * 128 + k0 + ac4 * 4];
            As[ac4 * 4 + 0][ar] = v.x;
            As[ac4 * 4 + 1][ar] = v.y;
            As[ac4 * 4 + 2][ar] = v.z;
            As[ac4 * 4 + 3][ar] = v.w;
        }
        #pragma unroll
        for (int l = 0; l < 2; l++) {
            int idx = tid + l * 256;
            int br  = idx >> 5;
            int bc4 = idx & 31;
            *(float4*)&Bs[br][bc4 * 4] = *(const float4*)&B[(k0 + br) * 128 + bc4 * 4];
        }
        __syncthreads();
        #pragma unroll
        for (int k = 0; k < BK; k++) {
            float a[8];
            *(float4*)&a[0] = *(const float4*)&As[k][trow * 8];
            *(float4*)&a[4] = *(const float4*)&As[k][trow * 8 + 4];
            unsigned long long b2[4];
            b2[0] = *(const unsigned long long*)&Bs[k][tcol * 4 + 0];
            b2[1] = *(const unsigned long long*)&Bs[k][tcol * 4 + 2];
            b2[2] = *(const unsigned long long*)&Bs[k][64 + tcol * 4 + 0];
            b2[3] = *(const unsigned long long*)&Bs[k][64 + tcol * 4 + 2];
            #pragma unroll
            for (int i = 0; i < 8; i++) {
                unsigned long long a2;
                asm("mov.b64 %0, {%1, %1};" : "=l"(a2) : "f"(a[i]));
                #pragma unroll
                for (int j = 0; j < 4; j++)
                    asm("fma.rn.f32x2 %0, %1, %2, %0;"
                        : "+l"(acc2[i][j]) : "l"(a2), "l"(b2[j]));
            }
        }
        __syncthreads();
    }
    #pragma unroll
    for (int i = 0; i < 8; i++) {
        int grow = block_row + trow * 8 + i;
        if (grow < nrows) {
            float4 v0, v1;
            asm("mov.b64 {%0,%1}, %2;" : "=f"(v0.x), "=f"(v0.y) : "l"(acc2[i][0]));
            asm("mov.b64 {%0,%1}, %2;" : "=f"(v0.z), "=f"(v0.w) : "l"(acc2[i][1]));
            asm("mov.b64 {%0,%1}, %2;" : "=f"(v1.x), "=f"(v1.y) : "l"(acc2[i][2]));
            asm("mov.b64 {%0,%1}, %2;" : "=f"(v1.z), "=f"(v1.w) : "l"(acc2[i][3]));
            *(float4*)&C[grow * 128 + tcol * 4]      = v0;
            *(float4*)&C[grow * 128 + 64 + tcol * 4] = v1;
        }
    }
}

// ---------------- stage 0: zero counts ----------------
__global__ void k_zero_counts() {
    int i = blockIdx.x * 256 + threadIdx.x;
    if (i < NN) g_cur[i] = 0;
}

// ---------------- stage 1: gemm(Wl) || hist + mean partials ----------------
__global__ __launch_bounds__(256) void k_gemm_hist(const float* __restrict__ A,
                                                   const float* __restrict__ B,
                                                   float* __restrict__ C,
                                                   const int* __restrict__ dst,
                                                   const float* __restrict__ ew) {
    if (blockIdx.x < GEMM_BLOCKS) {
        gemm_body(A, B, C, NN, blockIdx.x);
    } else {
        __shared__ float s[256];
        int hb = blockIdx.x - GEMM_BLOCKS;        // 0..HIST_BLOCKS-1
        int e  = hb * 256 + threadIdx.x;
        float w = 0.f;
        if (e < EE) {
            atomicAdd(&g_cur[dst[e]], 1);
            w = ew[e];
        }
        s[threadIdx.x] = w; __syncthreads();
        for (int o = 128; o > 0; o >>= 1) {
            if (threadIdx.x < o) s[threadIdx.x] += s[threadIdx.x + o];
            __syncthreads();
        }
        if (threadIdx.x == 0) g_partials[hb] = s[0];
    }
}

// ---------------- scan stage 1 ----------------
__global__ void k_scan1() {
    __shared__ int s[256];
    int tid = threadIdx.x;
    int i = blockIdx.x * 256 + tid;
    int v = (i < NN) ? g_cur[i] : 0;
    s[tid] = v; __syncthreads();
    for (int o = 1; o < 256; o <<= 1) {
        int t = (tid >= o) ? s[tid - o] : 0;
        __syncthreads();
        s[tid] += t;
        __syncthreads();
    }
    if (i < NN) g_rowptr[i] = s[tid];               // block-local inclusive (temp)
    if (tid == 255) g_blocksums[blockIdx.x] = s[255];
}

// ---------------- scan stage 2 || mean final (grid = 2) ----------------
__global__ void k_scan2_mean() {
    if (blockIdx.x == 0) {
        __shared__ int s[256];
        int tid = threadIdx.x;
        int v = (tid < SCAN_BLOCKS) ? g_blocksums[tid] : 0;
        s[tid] = v; __syncthreads();
        for (int o = 1; o < 256; o <<= 1) {
            int t = (tid >= o) ? s[tid - o] : 0;
            __syncthreads();
            s[tid] += t;
            __syncthreads();
        }
        g_blocksums[tid] = s[tid] - v;   // exclusive
    } else {
        __shared__ float s[256];
        float sum = 0.f;
        for (int i = threadIdx.x; i < HIST_BLOCKS; i += 256)
            sum += g_partials[i];
        s[threadIdx.x] = sum; __syncthreads();
        for (int o = 128; o > 0; o >>= 1) {
            if (threadIdx.x < o) s[threadIdx.x] += s[threadIdx.x + o];
            __syncthreads();
        }
        if (threadIdx.x == 0) g_mean = s[0] / (float)EE;
    }
}

// ---------------- scan stage 3 ----------------
__global__ void k_scan3() {
    int i = blockIdx.x * 256 + threadIdx.x;
    if (i < NN) {
        int excl = g_rowptr[i] - g_cur[i] + g_blocksums[blockIdx.x];
        g_rowptr[i] = excl;
        g_cur[i]    = excl;
    }
    if (blockIdx.x == 0 && threadIdx.x == 0) g_rowptr[NN] = EE;
}

// ---------------- stage 2: gemm(Wr) || scatter ----------------
__global__ __launch_bounds__(256) void k_gemm_scatter(const float* __restrict__ A,
                                                      const float* __restrict__ B,
                                                      float* __restrict__ C,
                                                      const int* __restrict__ src,
                                                      const int* __restrict__ dst,
                                                      const float* __restrict__ ew) {
    if (blockIdx.x < GEMM_BLOCKS) {
        gemm_body(A, B, C, NN, blockIdx.x);
    } else {
        int e = (blockIdx.x - GEMM_BLOCKS) * 256 + threadIdx.x;
        if (e < EE) {
            int d   = dst[e];
            int pos = atomicAdd(&g_cur[d], 1);
            g_edge[pos] = make_int2(src[e], __float_as_int(ew[e]));
        }
    }
}

// ---------------- layer-2 GEMM (both weights via blockIdx.y) ----------------
__global__ __launch_bounds__(256) void k_gemm2(const float* __restrict__ A,
                                               const float* __restrict__ B0,
                                               float* __restrict__ C0,
                                               const float* __restrict__ B1,
                                               float* __restrict__ C1) {
    if (blockIdx.y == 0) gemm_body(A, B0, C0, NN, blockIdx.x);
    else                 gemm_body(A, B1, C1, NN, blockIdx.x);
}

// ---------------- fused per-dst GATv2 edge pass (warp per node) ----------------
// lane holds channels 4*lane..4*lane+3 (head = lane>>3); per-head reduce = 3 shfl
__device__ __forceinline__ float edge_logit(float4 xs, float4 xr4, float4 we4,
                                            float4 at4, float w) {
    float z, p;
    z = fmaf(w, we4.x, xr4.x) + xs.x; z = fmaxf(z, 0.2f * z); p = z * at4.x;
    z = fmaf(w, we4.y, xr4.y) + xs.y; z = fmaxf(z, 0.2f * z); p = fmaf(z, at4.y, p);
    z = fmaf(w, we4.z, xr4.z) + xs.z; z = fmaxf(z, 0.2f * z); p = fmaf(z, at4.z, p);
    z = fmaf(w, we4.w, xr4.w) + xs.w; z = fmaxf(z, 0.2f * z); p = fmaf(z, at4.w, p);
    p += __shfl_xor_sync(0xffffffffu, p, 1);
    p += __shfl_xor_sync(0xffffffffu, p, 2);
    p += __shfl_xor_sync(0xffffffffu, p, 4);
    return p;   // uniform within each 8-lane (per-head) group
}

template <bool CONCAT>
__global__ __launch_bounds__(256) void k_edge(const float* __restrict__ xl,
                                              const float* __restrict__ xr,
                                              const float* __restrict__ We,
                                              const float* __restrict__ att,
                                              const float* __restrict__ bias,
                                              float* __restrict__ out) {
    int d = (blockIdx.x * 256 + threadIdx.x) >> 5;
    if (d >= NN) return;
    int lane = threadIdx.x & 31;

    float mean = g_mean;
    const float4 xr4 = *(const float4*)&xr[d * D + lane * 4];
    const float4 we4 = __ldg((const float4*)&We[lane * 4]);
    const float4 at4 = __ldg((const float4*)&att[lane * 4]);

    // self-loop seeds the online softmax
    float4 xs = *(const float4*)&xl[d * D + lane * 4];
    float m = edge_logit(xs, xr4, we4, at4, mean);
    float denom = 1.0f;
    float4 acc = xs;

    int beg = g_rowptr[d], end = g_rowptr[d + 1];
    int n = end - beg;
    int2 e0, e1; float4 x0, x1;
    e0 = e1 = make_int2(0, 0);
    x0 = x1 = make_float4(0.f, 0.f, 0.f, 0.f);
    if (n > 0) { e0 = g_edge[beg];     x0 = *(const float4*)&xl[e0.x * D + lane * 4]; }
    if (n > 1) { e1 = g_edge[beg + 1]; x1 = *(const float4*)&xl[e1.x * D + lane * 4]; }

    for (int i = beg; i < end; i++) {
        float  w  = __int_as_float(e0.y);
        float4 xc = x0;
        e0 = e1; x0 = x1;
        int j = i + 2;
        if (j < end) { e1 = g_edge[j]; x1 = *(const float4*)&xl[e1.x * D + lane * 4]; }

        float le = edge_logit(xc, xr4, we4, at4, w);
        float newm = fmaxf(m, le);
        float p = __expf(le - newm);
        float r = __expf(m  - newm);
        denom = fmaf(denom, r, p);
        acc.x = fmaf(acc.x, r, p * xc.x);
        acc.y = fmaf(acc.y, r, p * xc.y);
        acc.z = fmaf(acc.z, r, p * xc.z);
        acc.w = fmaf(acc.w, r, p * xc.w);
        m = newm;
    }

    float inv = 1.0f / (denom + 1e-16f);
    float4 o = make_float4(acc.x * inv, acc.y * inv, acc.z * inv, acc.w * inv);

    if (CONCAT) {
        const float4 b4 = __ldg((const float4*)&bias[lane * 4]);
        float4 v;
        v.x = o.x + b4.x; v.x = (v.x > 0.f) ? v.x : expm1f(v.x);
        v.y = o.y + b4.y; v.y = (v.y > 0.f) ? v.y : expm1f(v.y);
        v.z = o.z + b4.z; v.z = (v.z > 0.f) ? v.z : expm1f(v.z);
        v.w = o.w + b4.w; v.w = (v.w > 0.f) ? v.w : expm1f(v.w);
        *(float4*)&out[d * D + lane * 4] = v;
    } else {
        // mean over heads: lanes l, l^8, l^16, l^24 hold same within-head channel
        float s0 = o.x, s1 = o.y, s2 = o.z, s3 = o.w;
        s0 += __shfl_xor_sync(0xffffffffu, s0, 8);
        s1 += __shfl_xor_sync(0xffffffffu, s1, 8);
        s2 += __shfl_xor_sync(0xffffffffu, s2, 8);
        s3 += __shfl_xor_sync(0xffffffffu, s3, 8);
        s0 += __shfl_xor_sync(0xffffffffu, s0, 16);
        s1 += __shfl_xor_sync(0xffffffffu, s1, 16);
        s2 += __shfl_xor_sync(0xffffffffu, s2, 16);
        s3 += __shfl_xor_sync(0xffffffffu, s3, 16);
        if (lane < 8) {
            const float4 b4 = __ldg((const float4*)&bias[lane * 4]);
            float4 r;
            r.x = s0 * 0.25f + b4.x;
            r.y = s1 * 0.25f + b4.y;
            r.z = s2 * 0.25f + b4.z;
            r.w = s3 * 0.25f + b4.w;
            *(float4*)&out[d * CH + lane * 4] = r;
        }
    }
}

// ---------------- launch ----------------
static float* symaddr_f(const void* sym) {
    void* p = nullptr;
    cudaGetSymbolAddress(&p, sym);
    return (float*)p;
}

extern "C" void kernel_launch(void* const* d_in, const int* in_sizes, int n_in,
                              void* d_out, int out_size) {
    const float* x    = (const float*)d_in[0];
    const int*   ei   = (const int*)  d_in[1];
    const float* ew   = (const float*)d_in[2];
    const float* Wl1  = (const float*)d_in[3];
    const float* Wr1  = (const float*)d_in[4];
    const float* We1  = (const float*)d_in[5];
    const float* att1 = (const float*)d_in[6];
    const float* b1   = (const float*)d_in[7];
    const float* Wl2  = (const float*)d_in[8];
    const float* Wr2  = (const float*)d_in[9];
    const float* We2  = (const float*)d_in[10];
    const float* att2 = (const float*)d_in[11];
    const float* b2   = (const float*)d_in[12];
    float* out = (float*)d_out;

    const int* src = ei;
    const int* dst = ei + EE;

    float* xl = symaddr_f(g_xl);
    float* xr = symaddr_f(g_xr);
    float* h  = symaddr_f(g_h);

    const int edge_grid = (NN + 7) / 8;

    // stage 0: zero counts
    k_zero_counts<<<SCAN_BLOCKS, 256>>>();
    // stage 1: gemm(x*Wl1 -> xl)  ||  hist + mean partials
    k_gemm_hist<<<GEMM_BLOCKS + HIST_BLOCKS, 256>>>(x, Wl1, xl, dst, ew);
    // scan chain (tiny)
    k_scan1<<<SCAN_BLOCKS, 256>>>();
    k_scan2_mean<<<2, 256>>>();
    k_scan3<<<SCAN_BLOCKS, 256>>>();
    // stage 2: gemm(x*Wr1 -> xr)  ||  scatter edges into CSR
    k_gemm_scatter<<<GEMM_BLOCKS + HIST_BLOCKS, 256>>>(x, Wr1, xr, src, dst, ew);
    // layer-1 edge pass
    k_edge<true><<<edge_grid, 256>>>(xl, xr, We1, att1, b1, h);
    // layer-2 GEMMs (both weights)
    k_gemm2<<<dim3(GEMM_BLOCKS, 2), 256>>>(h, Wl2, xl, Wr2, xr);
    // layer-2 edge pass
    k_edge<false><<<edge_grid, 256>>>(xl, xr, We2, att2, b2, out);
}

// round 10
// speedup vs baseline: 1.4521x; 1.4521x over previous
#include <cuda_runtime.h>
#include <cuda_fp16.h>
#include <math.h>

#define NN 50000
#define EE 1600000
#define D  128       // H*C
#define CH 32
#define NH 4
#define SCAN_BLOCKS 196        // ceil(NN/256)
#define HIST_BLOCKS 6250       // ceil(EE/256)
#define GEMM_BLOCKS 391        // ceil(NN/128)

// ---------------- scratch (device globals; no allocation allowed) ----------------
__device__ __half g_xlh[NN * D];     // gathered operand, fp16 (halves L2 gather traffic)
__device__ float  g_xr[NN * D];
__device__ float  g_h [NN * D];
__device__ int    g_rowptr[NN + 1];
__device__ int    g_cur[NN];         // counts, then scatter cursors
__device__ int2   g_edge[EE];        // (src, bitcast(ew)) sorted by dst
__device__ int    g_blocksums[256];
__device__ float  g_partials[HIST_BLOCKS];
__device__ float  g_mean;

// ---------------- CSR build: zero counts ----------------
__global__ void k_zero_counts() {
    int i = blockIdx.x * 256 + threadIdx.x;
    if (i < NN) g_cur[i] = 0;
}

// ---------------- hist + mean partial in ONE pass (light kernel) ----------------
__global__ __launch_bounds__(256) void k_hist_mean(const int* __restrict__ dst,
                                                   const float* __restrict__ ew) {
    __shared__ float s[256];
    int e = blockIdx.x * 256 + threadIdx.x;
    float w = 0.f;
    if (e < EE) {
        atomicAdd(&g_cur[dst[e]], 1);
        w = ew[e];
    }
    s[threadIdx.x] = w; __syncthreads();
    for (int o = 128; o > 0; o >>= 1) {
        if (threadIdx.x < o) s[threadIdx.x] += s[threadIdx.x + o];
        __syncthreads();
    }
    if (threadIdx.x == 0) g_partials[blockIdx.x] = s[0];
}

// ---------------- multi-block scan ----------------
__global__ void k_scan1() {
    __shared__ int s[256];
    int tid = threadIdx.x;
    int i = blockIdx.x * 256 + tid;
    int v = (i < NN) ? g_cur[i] : 0;
    s[tid] = v; __syncthreads();
    for (int o = 1; o < 256; o <<= 1) {
        int t = (tid >= o) ? s[tid - o] : 0;
        __syncthreads();
        s[tid] += t;
        __syncthreads();
    }
    if (i < NN) g_rowptr[i] = s[tid];               // block-local inclusive (temp)
    if (tid == 255) g_blocksums[blockIdx.x] = s[255];
}

// scan stage 2 || mean final (grid = 2)
__global__ void k_scan2_mean() {
    if (blockIdx.x == 0) {
        __shared__ int s[256];
        int tid = threadIdx.x;
        int v = (tid < SCAN_BLOCKS) ? g_blocksums[tid] : 0;
        s[tid] = v; __syncthreads();
        for (int o = 1; o < 256; o <<= 1) {
            int t = (tid >= o) ? s[tid - o] : 0;
            __syncthreads();
            s[tid] += t;
            __syncthreads();
        }
        g_blocksums[tid] = s[tid] - v;   // exclusive
    } else {
        __shared__ float s[256];
        float sum = 0.f;
        for (int i = threadIdx.x; i < HIST_BLOCKS; i += 256)
            sum += g_partials[i];
        s[threadIdx.x] = sum; __syncthreads();
        for (int o = 128; o > 0; o >>= 1) {
            if (threadIdx.x < o) s[threadIdx.x] += s[threadIdx.x + o];
            __syncthreads();
        }
        if (threadIdx.x == 0) g_mean = s[0] / (float)EE;
    }
}

__global__ void k_scan3() {
    int i = blockIdx.x * 256 + threadIdx.x;
    if (i < NN) {
        int excl = g_rowptr[i] - g_cur[i] + g_blocksums[blockIdx.x];
        g_rowptr[i] = excl;
        g_cur[i]    = excl;
    }
    if (blockIdx.x == 0 && threadIdx.x == 0) g_rowptr[NN] = EE;
}

__global__ void k_scatter(const int* __restrict__ src, const int* __restrict__ dst,
                          const float* __restrict__ ew) {
    int e = blockIdx.x * 256 + threadIdx.x;
    if (e < EE) {
        int d   = dst[e];
        int pos = atomicAdd(&g_cur[d], 1);
        g_edge[pos] = make_int2(src[e], __float_as_int(ew[e]));
    }
}

// ---------------- SGEMM via packed f32x2 FFMA, templated output precision ----------------
// C[nrows x 128] = A[nrows x 128] * B[128 x 128], 256 threads/block
template <bool HALF_OUT>
__device__ __forceinline__ void gemm_body(const float* __restrict__ A,
                                          const float* __restrict__ B,
                                          void* __restrict__ Cv,
                                          int nrows, int bid) {
    const int BM = 128, BK = 16;
    __shared__ float As[BK][BM];
    __shared__ float Bs[BK][128];
    int tid = threadIdx.x;                 // 256
    int block_row = bid * BM;
    int tcol = tid & 15;                   // 16 col groups
    int trow = tid >> 4;                   // 16 row groups x 8
    unsigned long long acc2[8][4];
    #pragma unroll
    for (int i = 0; i < 8; i++)
        #pragma unroll
        for (int j = 0; j < 4; j++) acc2[i][j] = 0ULL;

    for (int k0 = 0; k0 < 128; k0 += BK) {
        #pragma unroll
        for (int l = 0; l < 2; l++) {
            int idx = tid + l * 256;        // 0..511 float4s
            int ar  = idx >> 2;
            int ac4 = idx & 3;
            int grow = block_row + ar;
            float4 v = make_float4(0.f, 0.f, 0.f, 0.f);
            if (grow < nrows) v = *(const float4*)&A[grow * 128 + k0 + ac4 * 4];
            As[ac4 * 4 + 0][ar] = v.x;
            As[ac4 * 4 + 1][ar] = v.y;
            As[ac4 * 4 + 2][ar] = v.z;
            As[ac4 * 4 + 3][ar] = v.w;
        }
        #pragma unroll
        for (int l = 0; l < 2; l++) {
            int idx = tid + l * 256;
            int br  = idx >> 5;
            int bc4 = idx & 31;
            *(float4*)&Bs[br][bc4 * 4] = *(const float4*)&B[(k0 + br) * 128 + bc4 * 4];
        }
        __syncthreads();
        #pragma unroll
        for (int k = 0; k < BK; k++) {
            float a[8];
            *(float4*)&a[0] = *(const float4*)&As[k][trow * 8];
            *(float4*)&a[4] = *(const float4*)&As[k][trow * 8 + 4];
            unsigned long long b2[4];
            b2[0] = *(const unsigned long long*)&Bs[k][tcol * 4 + 0];
            b2[1] = *(const unsigned long long*)&Bs[k][tcol * 4 + 2];
            b2[2] = *(const unsigned long long*)&Bs[k][64 + tcol * 4 + 0];
            b2[3] = *(const unsigned long long*)&Bs[k][64 + tcol * 4 + 2];
            #pragma unroll
            for (int i = 0; i < 8; i++) {
                unsigned long long a2;
                asm("mov.b64 %0, {%1, %1};" : "=l"(a2) : "f"(a[i]));
                #pragma unroll
                for (int j = 0; j < 4; j++)
                    asm("fma.rn.f32x2 %0, %1, %2, %0;"
                        : "+l"(acc2[i][j]) : "l"(a2), "l"(b2[j]));
            }
        }
        __syncthreads();
    }
    #pragma unroll
    for (int i = 0; i < 8; i++) {
        int grow = block_row + trow * 8 + i;
        if (grow < nrows) {
            float f[8];
            asm("mov.b64 {%0,%1}, %2;" : "=f"(f[0]), "=f"(f[1]) : "l"(acc2[i][0]));
            asm("mov.b64 {%0,%1}, %2;" : "=f"(f[2]), "=f"(f[3]) : "l"(acc2[i][1]));
            asm("mov.b64 {%0,%1}, %2;" : "=f"(f[4]), "=f"(f[5]) : "l"(acc2[i][2]));
            asm("mov.b64 {%0,%1}, %2;" : "=f"(f[6]), "=f"(f[7]) : "l"(acc2[i][3]));
            if (HALF_OUT) {
                __half* C = (__half*)Cv;
                __half2 h0 = __floats2half2_rn(f[0], f[1]);
                __half2 h1 = __floats2half2_rn(f[2], f[3]);
                __half2 h2 = __floats2half2_rn(f[4], f[5]);
                __half2 h3 = __floats2half2_rn(f[6], f[7]);
                *(__half2*)&C[grow * 128 + tcol * 4 + 0]      = h0;
                *(__half2*)&C[grow * 128 + tcol * 4 + 2]      = h1;
                *(__half2*)&C[grow * 128 + 64 + tcol * 4 + 0] = h2;
                *(__half2*)&C[grow * 128 + 64 + tcol * 4 + 2] = h3;
            } else {
                float* C = (float*)Cv;
                *(float4*)&C[grow * 128 + tcol * 4]      = make_float4(f[0], f[1], f[2], f[3]);
                *(float4*)&C[grow * 128 + 64 + tcol * 4] = make_float4(f[4], f[5], f[6], f[7]);
            }
        }
    }
}

// dual GEMM: y==0 -> A*B0 -> half C0 (gather operand), y==1 -> A*B1 -> float C1
__global__ __launch_bounds__(256) void k_gemm_dual(const float* __restrict__ A,
                                                   const float* __restrict__ B0,
                                                   __half* __restrict__ C0,
                                                   const float* __restrict__ B1,
                                                   float* __restrict__ C1) {
    if (blockIdx.y == 0) gemm_body<true >(A, B0, (void*)C0, NN, blockIdx.x);
    else                 gemm_body<false>(A, B1, (void*)C1, NN, blockIdx.x);
}

// ---------------- fused per-dst GATv2 edge pass (warp per node) ----------------
// lane holds channels 4*lane..4*lane+3 (head = lane>>3); per-head reduce = 3 shfl
__device__ __forceinline__ float edge_logit(float4 xs, float4 xr4, float4 we4,
                                            float4 at4, float w) {
    float z, p;
    z = fmaf(w, we4.x, xr4.x) + xs.x; z = fmaxf(z, 0.2f * z); p = z * at4.x;
    z = fmaf(w, we4.y, xr4.y) + xs.y; z = fmaxf(z, 0.2f * z); p = fmaf(z, at4.y, p);
    z = fmaf(w, we4.z, xr4.z) + xs.z; z = fmaxf(z, 0.2f * z); p = fmaf(z, at4.z, p);
    z = fmaf(w, we4.w, xr4.w) + xs.w; z = fmaxf(z, 0.2f * z); p = fmaf(z, at4.w, p);
    p += __shfl_xor_sync(0xffffffffu, p, 1);
    p += __shfl_xor_sync(0xffffffffu, p, 2);
    p += __shfl_xor_sync(0xffffffffu, p, 4);
    return p;   // uniform within each 8-lane (per-head) group
}

__device__ __forceinline__ float4 load_half4(const __half* __restrict__ p) {
    uint2 raw = *(const uint2*)p;
    __half2 h0 = *(__half2*)&raw.x;
    __half2 h1 = *(__half2*)&raw.y;
    float2 f0 = __half22float2(h0);
    float2 f1 = __half22float2(h1);
    return make_float4(f0.x, f0.y, f1.x, f1.y);
}

template <bool CONCAT>
__global__ __launch_bounds__(256) void k_edge(const __half* __restrict__ xl,
                                              const float* __restrict__ xr,
                                              const float* __restrict__ We,
                                              const float* __restrict__ att,
                                              const float* __restrict__ bias,
                                              float* __restrict__ out) {
    int d = (blockIdx.x * 256 + threadIdx.x) >> 5;
    if (d >= NN) return;
    int lane = threadIdx.x & 31;

    float mean = g_mean;
    const float4 xr4 = *(const float4*)&xr[d * D + lane * 4];
    const float4 we4 = __ldg((const float4*)&We[lane * 4]);
    const float4 at4 = __ldg((const float4*)&att[lane * 4]);

    // self-loop seeds the online softmax
    float4 xs = load_half4(&xl[d * D + lane * 4]);
    float m = edge_logit(xs, xr4, we4, at4, mean);
    float denom = 1.0f;
    float4 acc = xs;

    int beg = g_rowptr[d], end = g_rowptr[d + 1];
    int n = end - beg;
    int2 e0, e1; float4 x0, x1;
    e0 = e1 = make_int2(0, 0);
    x0 = x1 = make_float4(0.f, 0.f, 0.f, 0.f);
    if (n > 0) { e0 = g_edge[beg];     x0 = load_half4(&xl[e0.x * D + lane * 4]); }
    if (n > 1) { e1 = g_edge[beg + 1]; x1 = load_half4(&xl[e1.x * D + lane * 4]); }

    for (int i = beg; i < end; i++) {
        float  w  = __int_as_float(e0.y);
        float4 xc = x0;
        e0 = e1; x0 = x1;
        int j = i + 2;
        if (j < end) { e1 = g_edge[j]; x1 = load_half4(&xl[e1.x * D + lane * 4]); }

        float le = edge_logit(xc, xr4, we4, at4, w);
        float newm = fmaxf(m, le);
        float p = __expf(le - newm);
        float r = __expf(m  - newm);
        denom = fmaf(denom, r, p);
        acc.x = fmaf(acc.x, r, p * xc.x);
        acc.y = fmaf(acc.y, r, p * xc.y);
        acc.z = fmaf(acc.z, r, p * xc.z);
        acc.w = fmaf(acc.w, r, p * xc.w);
        m = newm;
    }

    float inv = 1.0f / (denom + 1e-16f);
    float4 o = make_float4(acc.x * inv, acc.y * inv, acc.z * inv, acc.w * inv);

    if (CONCAT) {
        const float4 b4 = __ldg((const float4*)&bias[lane * 4]);
        float4 v;
        v.x = o.x + b4.x; v.x = (v.x > 0.f) ? v.x : expm1f(v.x);
        v.y = o.y + b4.y; v.y = (v.y > 0.f) ? v.y : expm1f(v.y);
        v.z = o.z + b4.z; v.z = (v.z > 0.f) ? v.z : expm1f(v.z);
        v.w = o.w + b4.w; v.w = (v.w > 0.f) ? v.w : expm1f(v.w);
        *(float4*)&out[d * D + lane * 4] = v;
    } else {
        // mean over heads: lanes l, l^8, l^16, l^24 hold same within-head channel
        float s0 = o.x, s1 = o.y, s2 = o.z, s3 = o.w;
        s0 += __shfl_xor_sync(0xffffffffu, s0, 8);
        s1 += __shfl_xor_sync(0xffffffffu, s1, 8);
        s2 += __shfl_xor_sync(0xffffffffu, s2, 8);
        s3 += __shfl_xor_sync(0xffffffffu, s3, 8);
        s0 += __shfl_xor_sync(0xffffffffu, s0, 16);
        s1 += __shfl_xor_sync(0xffffffffu, s1, 16);
        s2 += __shfl_xor_sync(0xffffffffu, s2, 16);
        s3 += __shfl_xor_sync(0xffffffffu, s3, 16);
        if (lane < 8) {
            const float4 b4 = __ldg((const float4*)&bias[lane * 4]);
            float4 r;
            r.x = s0 * 0.25f + b4.x;
            r.y = s1 * 0.25f + b4.y;
            r.z = s2 * 0.25f + b4.z;
            r.w = s3 * 0.25f + b4.w;
            *(float4*)&out[d * CH + lane * 4] = r;
        }
    }
}

// ---------------- launch ----------------
static void* symaddr(const void* sym) {
    void* p = nullptr;
    cudaGetSymbolAddress(&p, sym);
    return p;
}

extern "C" void kernel_launch(void* const* d_in, const int* in_sizes, int n_in,
                              void* d_out, int out_size) {
    const float* x    = (const float*)d_in[0];
    const int*   ei   = (const int*)  d_in[1];
    const float* ew   = (const float*)d_in[2];
    const float* Wl1  = (const float*)d_in[3];
    const float* Wr1  = (const float*)d_in[4];
    const float* We1  = (const float*)d_in[5];
    const float* att1 = (const float*)d_in[6];
    const float* b1   = (const float*)d_in[7];
    const float* Wl2  = (const float*)d_in[8];
    const float* Wr2  = (const float*)d_in[9];
    const float* We2  = (const float*)d_in[10];
    const float* att2 = (const float*)d_in[11];
    const float* b2   = (const float*)d_in[12];
    float* out = (float*)d_out;

    const int* src = ei;
    const int* dst = ei + EE;

    __half* xlh = (__half*)symaddr(g_xlh);
    float*  xr  = (float*) symaddr(g_xr);
    float*  h   = (float*) symaddr(g_h);

    const int edge_grid = (NN + 7) / 8;

    // CSR build + mean (light kernels, low regs, full occupancy)
    k_zero_counts<<<SCAN_BLOCKS, 256>>>();
    k_hist_mean<<<HIST_BLOCKS, 256>>>(dst, ew);
    k_scan1<<<SCAN_BLOCKS, 256>>>();
    k_scan2_mean<<<2, 256>>>();
    k_scan3<<<SCAN_BLOCKS, 256>>>();
    k_scatter<<<HIST_BLOCKS, 256>>>(src, dst, ew);

    // layer 1: xl (half, gathered) + xr (float) in one launch
    k_gemm_dual<<<dim3(GEMM_BLOCKS, 2), 256>>>(x, Wl1, xlh, Wr1, xr);
    k_edge<true><<<edge_grid, 256>>>(xlh, xr, We1, att1, b1, h);

    // layer 2
    k_gemm_dual<<<dim3(GEMM_BLOCKS, 2), 256>>>(h, Wl2, xlh, Wr2, xr);
    k_edge<false><<<edge_grid, 256>>>(xlh, xr, We2, att2, b2, out);
}

// round 12
// speedup vs baseline: 1.5674x; 1.0794x over previous
#include <cuda_runtime.h>
#include <cuda_bf16.h>
#include <math.h>

#define NN 50000
#define EE 1600000
#define D  128       // H*C
#define CH 32
#define NH 4
#define SCAN_BLOCKS 196        // ceil(NN/256)
#define HIST_BLOCKS 6250       // ceil(EE/256)
#define GEMM_BLOCKS 391        // ceil(NN/128)

// ---------------- scratch (device globals; no allocation allowed) ----------------
__device__ float g_xl[NN * D];
__device__ float g_xr[NN * D];
__device__ float g_h [NN * D];
__device__ int   g_rowptr[NN + 1];
__device__ int   g_cur[NN];          // counts, then scatter cursors
__device__ int2  g_edge[EE];         // (src, bitcast(ew)) sorted by dst
__device__ int   g_blocksums[256];
__device__ float g_partials[HIST_BLOCKS];
__device__ float g_mean;

// ---------------- CSR build: zero counts ----------------
__global__ void k_zero_counts() {
    int i = blockIdx.x * 256 + threadIdx.x;
    if (i < NN) g_cur[i] = 0;
}

// ---------------- hist + mean partial in ONE pass (light kernel) ----------------
__global__ __launch_bounds__(256) void k_hist_mean(const int* __restrict__ dst,
                                                   const float* __restrict__ ew) {
    __shared__ float s[256];
    int e = blockIdx.x * 256 + threadIdx.x;
    float w = 0.f;
    if (e < EE) {
        atomicAdd(&g_cur[dst[e]], 1);
        w = ew[e];
    }
    s[threadIdx.x] = w; __syncthreads();
    for (int o = 128; o > 0; o >>= 1) {
        if (threadIdx.x < o) s[threadIdx.x] += s[threadIdx.x + o];
        __syncthreads();
    }
    if (threadIdx.x == 0) g_partials[blockIdx.x] = s[0];
}

// ---------------- multi-block scan ----------------
__global__ void k_scan1() {
    __shared__ int s[256];
    int tid = threadIdx.x;
    int i = blockIdx.x * 256 + tid;
    int v = (i < NN) ? g_cur[i] : 0;
    s[tid] = v; __syncthreads();
    for (int o = 1; o < 256; o <<= 1) {
        int t = (tid >= o) ? s[tid - o] : 0;
        __syncthreads();
        s[tid] += t;
        __syncthreads();
    }
    if (i < NN) g_rowptr[i] = s[tid];               // block-local inclusive (temp)
    if (tid == 255) g_blocksums[blockIdx.x] = s[255];
}

// scan stage 2 || mean final (grid = 2)
__global__ void k_scan2_mean() {
    if (blockIdx.x == 0) {
        __shared__ int s[256];
        int tid = threadIdx.x;
        int v = (tid < SCAN_BLOCKS) ? g_blocksums[tid] : 0;
        s[tid] = v; __syncthreads();
        for (int o = 1; o < 256; o <<= 1) {
            int t = (tid >= o) ? s[tid - o] : 0;
            __syncthreads();
            s[tid] += t;
            __syncthreads();
        }
        g_blocksums[tid] = s[tid] - v;   // exclusive
    } else {
        __shared__ float s[256];
        float sum = 0.f;
        for (int i = threadIdx.x; i < HIST_BLOCKS; i += 256)
            sum += g_partials[i];
        s[threadIdx.x] = sum; __syncthreads();
        for (int o = 128; o > 0; o >>= 1) {
            if (threadIdx.x < o) s[threadIdx.x] += s[threadIdx.x + o];
            __syncthreads();
        }
        if (threadIdx.x == 0) g_mean = s[0] / (float)EE;
    }
}

__global__ void k_scan3() {
    int i = blockIdx.x * 256 + threadIdx.x;
    if (i < NN) {
        int excl = g_rowptr[i] - g_cur[i] + g_blocksums[blockIdx.x];
        g_rowptr[i] = excl;
        g_cur[i]    = excl;
    }
    if (blockIdx.x == 0 && threadIdx.x == 0) g_rowptr[NN] = EE;
}

__global__ void k_scatter(const int* __restrict__ src, const int* __restrict__ dst,
                          const float* __restrict__ ew) {
    int e = blockIdx.x * 256 + threadIdx.x;
    if (e < EE) {
        int d   = dst[e];
        int pos = atomicAdd(&g_cur[d], 1);
        g_edge[pos] = make_int2(src[e], __float_as_int(ew[e]));
    }
}

// ---------------- SGEMM via packed f32x2 FFMA ----------------
// C[nrows x 128] = A[nrows x 128] * B[128 x 128], 256 threads/block
__device__ __forceinline__ void gemm_body(const float* __restrict__ A,
                                          const float* __restrict__ B,
                                          float* __restrict__ C,
                                          int nrows, int bid) {
    const int BM = 128, BK = 16;
    __shared__ float As[BK][BM];
    __shared__ float Bs[BK][128];
    int tid = threadIdx.x;                 // 256
    int block_row = bid * BM;
    int tcol = tid & 15;                   // 16 col groups
    int trow = tid >> 4;                   // 16 row groups x 8
    unsigned long long acc2[8][4];
    #pragma unroll
    for (int i = 0; i < 8; i++)
        #pragma unroll
        for (int j = 0; j < 4; j++) acc2[i][j] = 0ULL;

    for (int k0 = 0; k0 < 128; k0 += BK) {
        #pragma unroll
        for (int l = 0; l < 2; l++) {
            int idx = tid + l * 256;        // 0..511 float4s
            int ar  = idx >> 2;
            int ac4 = idx & 3;
            int grow = block_row + ar;
            float4 v = make_float4(0.f, 0.f, 0.f, 0.f);
            if (grow < nrows) v = *(const float4*)&A[grow * 128 + k0 + ac4 * 4];
            As[ac4 * 4 + 0][ar] = v.x;
            As[ac4 * 4 + 1][ar] = v.y;
            As[ac4 * 4 + 2][ar] = v.z;
            As[ac4 * 4 + 3][ar] = v.w;
        }
        #pragma unroll
        for (int l = 0; l < 2; l++) {
            int idx = tid + l * 256;
            int br  = idx >> 5;
            int bc4 = idx & 31;
            *(float4*)&Bs[br][bc4 * 4] = *(const float4*)&B[(k0 + br) * 128 + bc4 * 4];
        }
        __syncthreads();
        #pragma unroll
        for (int k = 0; k < BK; k++) {
            float a[8];
            *(float4*)&a[0] = *(const float4*)&As[k][trow * 8];
            *(float4*)&a[4] = *(const float4*)&As[k][trow * 8 + 4];
            unsigned long long b2[4];
            b2[0] = *(const unsigned long long*)&Bs[k][tcol * 4 + 0];
            b2[1] = *(const unsigned long long*)&Bs[k][tcol * 4 + 2];
            b2[2] = *(const unsigned long long*)&Bs[k][64 + tcol * 4 + 0];
            b2[3] = *(const unsigned long long*)&Bs[k][64 + tcol * 4 + 2];
            #pragma unroll
            for (int i = 0; i < 8; i++) {
                unsigned long long a2;
                asm("mov.b64 %0, {%1, %1};" : "=l"(a2) : "f"(a[i]));
                #pragma unroll
                for (int j = 0; j < 4; j++)
                    asm("fma.rn.f32x2 %0, %1, %2, %0;"
                        : "+l"(acc2[i][j]) : "l"(a2), "l"(b2[j]));
            }
        }
        __syncthreads();
    }
    #pragma unroll
    for (int i = 0; i < 8; i++) {
        int grow = block_row + trow * 8 + i;
        if (grow < nrows) {
            float4 v0, v1;
            asm("mov.b64 {%0,%1}, %2;" : "=f"(v0.x), "=f"(v0.y) : "l"(acc2[i][0]));
            asm("mov.b64 {%0,%1}, %2;" : "=f"(v0.z), "=f"(v0.w) : "l"(acc2[i][1]));
            asm("mov.b64 {%0,%1}, %2;" : "=f"(v1.x), "=f"(v1.y) : "l"(acc2[i][2]));
            asm("mov.b64 {%0,%1}, %2;" : "=f"(v1.z), "=f"(v1.w) : "l"(acc2[i][3]));
            *(float4*)&C[grow * 128 + tcol * 4]      = v0;
            *(float4*)&C[grow * 128 + 64 + tcol * 4] = v1;
        }
    }
}

// dual GEMM: one launch computes A*B0 -> C0 and A*B1 -> C1 via blockIdx.y
__global__ __launch_bounds__(256) void k_gemm_dual(const float* __restrict__ A,
                                                   const float* __restrict__ B0,
                                                   float* __restrict__ C0,
                                                   const float* __restrict__ B1,
                                                   float* __restrict__ C1) {
    if (blockIdx.y == 0) gemm_body(A, B0, C0, NN, blockIdx.x);
    else                 gemm_body(A, B1, C1, NN, blockIdx.x);
}

// ---------------- fused per-dst GATv2 edge pass (warp per node) ----------------
// lane holds channels 4*lane..4*lane+3 (head = lane>>3); per-head reduce = 3 shfl
__device__ __forceinline__ float edge_logit(float4 xs, float4 xr4, float4 we4,
                                            float4 at4, float w) {
    float z, p;
    z = fmaf(w, we4.x, xr4.x) + xs.x; z = fmaxf(z, 0.2f * z); p = z * at4.x;
    z = fmaf(w, we4.y, xr4.y) + xs.y; z = fmaxf(z, 0.2f * z); p = fmaf(z, at4.y, p);
    z = fmaf(w, we4.z, xr4.z) + xs.z; z = fmaxf(z, 0.2f * z); p = fmaf(z, at4.z, p);
    z = fmaf(w, we4.w, xr4.w) + xs.w; z = fmaxf(z, 0.2f * z); p = fmaf(z, at4.w, p);
    p += __shfl_xor_sync(0xffffffffu, p, 1);
    p += __shfl_xor_sync(0xffffffffu, p, 2);
    p += __shfl_xor_sync(0xffffffffu, p, 4);
    return p;   // uniform within each 8-lane (per-head) group
}

template <bool CONCAT>
__global__ __launch_bounds__(256) void k_edge(const float* __restrict__ xl,
                                              const float* __restrict__ xr,
                                              const float* __restrict__ We,
                                              const float* __restrict__ att,
                                              const float* __restrict__ bias,
                                              float* __restrict__ out) {
    int d = (blockIdx.x * 256 + threadIdx.x) >> 5;
    if (d >= NN) return;
    int lane = threadIdx.x & 31;

    float mean = g_mean;
    const float4 xr4 = *(const float4*)&xr[d * D + lane * 4];
    const float4 we4 = __ldg((const float4*)&We[lane * 4]);
    const float4 at4 = __ldg((const float4*)&att[lane * 4]);

    // self-loop seeds the online softmax
    float4 xs = *(const float4*)&xl[d * D + lane * 4];
    float m = edge_logit(xs, xr4, we4, at4, mean);
    float denom = 1.0f;
    float4 acc = xs;

    int beg = g_rowptr[d], end = g_rowptr[d + 1];
    int n = end - beg;
    int2 e0, e1; float4 x0, x1;
    e0 = e1 = make_int2(0, 0);
    x0 = x1 = make_float4(0.f, 0.f, 0.f, 0.f);
    if (n > 0) { e0 = g_edge[beg];     x0 = *(const float4*)&xl[e0.x * D + lane * 4]; }
    if (n > 1) { e1 = g_edge[beg + 1]; x1 = *(const float4*)&xl[e1.x * D + lane * 4]; }

    for (int i = beg; i < end; i++) {
        float  w  = __int_as_float(e0.y);
        float4 xc = x0;
        e0 = e1; x0 = x1;
        int j = i + 2;
        if (j < end) { e1 = g_edge[j]; x1 = *(const float4*)&xl[e1.x * D + lane * 4]; }

        float le = edge_logit(xc, xr4, we4, at4, w);
        // single-exp online update: one of p/r is exactly 1
        float t  = le - m;
        float e  = __expf(-fabsf(t));
        bool  up = (t > 0.f);
        float p  = up ? 1.f : e;
        float r  = up ? e   : 1.f;
        m        = up ? le  : m;
        denom = fmaf(denom, r, p);
        acc.x = fmaf(acc.x, r, p * xc.x);
        acc.y = fmaf(acc.y, r, p * xc.y);
        acc.z = fmaf(acc.z, r, p * xc.z);
        acc.w = fmaf(acc.w, r, p * xc.w);
    }

    float inv = 1.0f / (denom + 1e-16f);
    float4 o = make_float4(acc.x * inv, acc.y * inv, acc.z * inv, acc.w * inv);

    if (CONCAT) {
        const float4 b4 = __ldg((const float4*)&bias[lane * 4]);
        float4 v;
        v.x = o.x + b4.x; v.x = (v.x > 0.f) ? v.x : expm1f(v.x);
        v.y = o.y + b4.y; v.y = (v.y > 0.f) ? v.y : expm1f(v.y);
        v.z = o.z + b4.z; v.z = (v.z > 0.f) ? v.z : expm1f(v.z);
        v.w = o.w + b4.w; v.w = (v.w > 0.f) ? v.w : expm1f(v.w);
        *(float4*)&out[d * D + lane * 4] = v;
    } else {
        // mean over heads: lanes l, l^8, l^16, l^24 hold same within-head channel
        float s0 = o.x, s1 = o.y, s2 = o.z, s3 = o.w;
        s0 += __shfl_xor_sync(0xffffffffu, s0, 8);
        s1 += __shfl_xor_sync(0xffffffffu, s1, 8);
        s2 += __shfl_xor_sync(0xffffffffu, s2, 8);
        s3 += __shfl_xor_sync(0xffffffffu, s3, 8);
        s0 += __shfl_xor_sync(0xffffffffu, s0, 16);
        s1 += __shfl_xor_sync(0xffffffffu, s1, 16);
        s2 += __shfl_xor_sync(0xffffffffu, s2, 16);
        s3 += __shfl_xor_sync(0xffffffffu, s3, 16);
        if (lane < 8) {
            const float4 b4 = __ldg((const float4*)&bias[lane * 4]);
            float4 r;
            r.x = s0 * 0.25f + b4.x;
            r.y = s1 * 0.25f + b4.y;
            r.z = s2 * 0.25f + b4.z;
            r.w = s3 * 0.25f + b4.w;
            *(float4*)&out[d * CH + lane * 4] = r;
        }
    }
}

// ---------------- launch ----------------
static void* symaddr(const void* sym) {
    void* p = nullptr;
    cudaGetSymbolAddress(&p, sym);
    return p;
}

extern "C" void kernel_launch(void* const* d_in, const int* in_sizes, int n_in,
                              void* d_out, int out_size) {
    const float* x    = (const float*)d_in[0];
    const int*   ei   = (const int*)  d_in[1];
    const float* ew   = (const float*)d_in[2];
    const float* Wl1  = (const float*)d_in[3];
    const float* Wr1  = (const float*)d_in[4];
    const float* We1  = (const float*)d_in[5];
    const float* att1 = (const float*)d_in[6];
    const float* b1   = (const float*)d_in[7];
    const float* Wl2  = (const float*)d_in[8];
    const float* Wr2  = (const float*)d_in[9];
    const float* We2  = (const float*)d_in[10];
    const float* att2 = (const float*)d_in[11];
    const float* b2   = (const float*)d_in[12];
    float* out = (float*)d_out;

    const int* src = ei;
    const int* dst = ei + EE;

    float* xl = (float*)symaddr(g_xl);
    float* xr = (float*)symaddr(g_xr);
    float* h  = (float*)symaddr(g_h);

    const int edge_grid = (NN + 7) / 8;

    // CSR build + mean (light kernels, low regs, full occupancy)
    k_zero_counts<<<SCAN_BLOCKS, 256>>>();
    k_hist_mean<<<HIST_BLOCKS, 256>>>(dst, ew);
    k_scan1<<<SCAN_BLOCKS, 256>>>();
    k_scan2_mean<<<2, 256>>>();
    k_scan3<<<SCAN_BLOCKS, 256>>>();
    k_scatter<<<HIST_BLOCKS, 256>>>(src, dst, ew);

    // layer 1
    k_gemm_dual<<<dim3(GEMM_BLOCKS, 2), 256>>>(x, Wl1, xl, Wr1, xr);
    k_edge<true><<<edge_grid, 256>>>(xl, xr, We1, att1, b1, h);

    // layer 2
    k_gemm_dual<<<dim3(GEMM_BLOCKS, 2), 256>>>(h, Wl2, xl, Wr2, xr);
    k_edge<false><<<edge_grid, 256>>>(xl, xr, We2, att2, b2, out);
}